// round 13
// baseline (speedup 1.0000x reference)
#include <cuda_runtime.h>
#include <cuda_fp16.h>
#include <math.h>
#include <stdint.h>

#define BN   8
#define CIN  32
#define COUT 32
#define HW   384
#define AUX  128
#define HID  256
#define MODOUT (COUT*CIN*9)   // 9216
#define KDIM 288              // k = tap*32 + ci
#define WST  296              // padded W row stride (conflict-free ldmatrix)

// Scratch (allocation-free rule: __device__ globals)
__device__ float g_bias[BN * COUT];
__device__ float g_h[BN * 2 * HID];        // [n][branch][HID]
__device__ __half g_w[BN * COUT * KDIM];   // [n][co][tap*32+ci] fp16

// ---------------------------------------------------------------------------
// warp-MMA helpers (sm_80-class, valid on compute_103 without 'a')
// ---------------------------------------------------------------------------
__device__ __forceinline__ uint32_t smem_u32(const void* p) {
    uint32_t a;
    asm("{ .reg .u64 t; cvta.to.shared.u64 t, %1; cvt.u32.u64 %0, t; }"
        : "=r"(a) : "l"(p));
    return a;
}
__device__ __forceinline__ void ldm4(uint32_t r[4], uint32_t addr) {
    asm volatile("ldmatrix.sync.aligned.m8n8.x4.shared.b16 {%0,%1,%2,%3}, [%4];"
        : "=r"(r[0]), "=r"(r[1]), "=r"(r[2]), "=r"(r[3]) : "r"(addr));
}
__device__ __forceinline__ void mma_f16(float d[4], const uint32_t a[4],
                                        const uint32_t b[2]) {
    asm volatile("mma.sync.aligned.m16n8k16.row.col.f32.f16.f16.f32 "
        "{%0,%1,%2,%3}, {%4,%5,%6,%7}, {%8,%9}, {%0,%1,%2,%3};"
        : "+f"(d[0]), "+f"(d[1]), "+f"(d[2]), "+f"(d[3])
        : "r"(a[0]), "r"(a[1]), "r"(a[2]), "r"(a[3]), "r"(b[0]), "r"(b[1]));
}

// ---------------------------------------------------------------------------
// MLP kernel 1: hidden layers. grid 32, block 128, ILP-8 (round-11 version).
// ---------------------------------------------------------------------------
__global__ void mlp_hidden(const float* __restrict__ y,
                           const float* __restrict__ fc_w1, const float* __restrict__ fc_b1,
                           const float* __restrict__ fc_a_p,
                           const float* __restrict__ b_w1,  const float* __restrict__ b_b1,
                           const float* __restrict__ b_a_p)
{
    __shared__ float y_s[AUX];
    const int b  = blockIdx.x;
    const int n  = b >> 2;
    const int br = (b >> 1) & 1;
    const int hf = b & 1;
    const int t  = threadIdx.x;

    y_s[t] = y[n*AUX + t];
    __syncthreads();

    const float* w1 = br ? b_w1 : fc_w1;
    const float* b1 = br ? b_b1 : fc_b1;
    const float  a  = br ? *b_a_p : *fc_a_p;
    const int col = hf*128 + t;

    float acc[8] = {0,0,0,0,0,0,0,0};
    #pragma unroll
    for (int i = 0; i < AUX; i += 8) {
        #pragma unroll
        for (int q = 0; q < 8; q++)
            acc[q] = fmaf(y_s[i+q], w1[(i+q)*HID + col], acc[q]);
    }
    const float h = ((acc[0]+acc[1])+(acc[2]+acc[3]))
                  + ((acc[4]+acc[5])+(acc[6]+acc[7])) + b1[col];
    g_h[(n*2 + br)*HID + col] = (h >= 0.f) ? h : a*h;
}

// ---------------------------------------------------------------------------
// MLP kernel 2: output layers. grid 289, block 512, ILP-16.
// ---------------------------------------------------------------------------
__global__ void mlp_out(const float* __restrict__ weight,
                        const float* __restrict__ fc_w2, const float* __restrict__ fc_b2,
                        const float* __restrict__ b_w2,  const float* __restrict__ b_b2)
{
    __shared__ float h_s[BN * HID];
    __shared__ float part[512];
    const int t = threadIdx.x;

    if (blockIdx.x < 288) {
        #pragma unroll
        for (int i = t; i < BN*HID; i += 512)
            h_s[i] = g_h[((i >> 8)*2)*HID + (i & 255)];
        __syncthreads();

        const int hf = t >> 8;              // HID half
        const int tt = t & 255;
        const int n  = tt >> 5;
        const int j  = blockIdx.x*32 + (tt & 31);
        const float* hp = h_s + n*HID + hf*128;
        const float* wp = fc_w2 + (size_t)(hf*128)*MODOUT + j;

        float m[16];
        #pragma unroll
        for (int q = 0; q < 16; q++) m[q] = 0.f;
        #pragma unroll
        for (int hh = 0; hh < 128; hh += 16) {
            #pragma unroll
            for (int q = 0; q < 16; q++)
                m[q] = fmaf(hp[hh+q], wp[(size_t)(hh+q)*MODOUT], m[q]);
        }
        float s = 0.f;
        #pragma unroll
        for (int q = 0; q < 16; q++) s += m[q];
        part[t] = s;
        __syncthreads();

        if (t < 256) {
            const float mm = part[t] + part[t+256] + fc_b2[j];
            const float sg = 1.f / (1.f + expf(-mm));
            const float wm = sg * weight[j];
            const int co  = j / 288;
            const int r   = j - co*288;
            const int ci  = r / 9;
            const int tap = r - ci*9;
            const int nn  = t >> 5;
            g_w[(nn*COUT + co)*KDIM + tap*32 + ci] = __float2half_rn(wm);
        }
    } else {
        #pragma unroll
        for (int i = t; i < BN*HID; i += 512)
            h_s[i] = g_h[((i >> 8)*2 + 1)*HID + (i & 255)];
        __syncthreads();

        if (t < 256) {
            const int n  = t >> 5;
            const int co = t & 31;
            const float* hb = h_s + n*HID;
            float m[8];
            #pragma unroll
            for (int q = 0; q < 8; q++) m[q] = 0.f;
            #pragma unroll
            for (int hh = 0; hh < HID; hh += 8) {
                #pragma unroll
                for (int q = 0; q < 8; q++)
                    m[q] = fmaf(hb[hh+q], b_w2[(hh+q)*COUT + co], m[q]);
            }
            float s = 0.f;
            #pragma unroll
            for (int q = 0; q < 8; q++) s += m[q];
            g_bias[n*COUT + co] = s + b_b2[co];
        }
    }
}

// ---------------------------------------------------------------------------
// Conv: mma.sync fp16 single-pass, 4-ROW OUTPUT BLOCKING, 2 CTAs/SM.
// Per kwh window a warp computes 4 rows (48 mma) from 3 A-ldmatrix (24 wf)
// + 6 B-ldmatrix (24 wf): 1.0 wf/mma (was 1.67). A held in 3 reg buffers.
// Slab: 8-slot rolling window; strip = 16 rows (4 quads).
// ---------------------------------------------------------------------------
#define RC       130
#define CIP      40
#define NSLOT    8
#define SLAB_B   (NSLOT*RC*CIP*2)          // 83200
#define W_BYTES  (COUT*WST*2)              // 18944
#define OFF_W    0
#define OFF_X    (W_BYTES)                 // 18944
#define CONV_SMEM (OFF_X + SLAB_B)         // 102144 -> 2 CTAs/SM
#define NSTG     9                         // ceil(16*RC/256)

__device__ __forceinline__ void stage_row(const float* __restrict__ xn,
                                          uint32_t* __restrict__ xs32,
                                          int gy, int x0, int tid)
{
    const int slot = (gy + NSLOT) & (NSLOT - 1);
    const bool yok = (unsigned)gy < (unsigned)HW;
    float v0[NSTG], v1[NSTG];
    #pragma unroll
    for (int it = 0; it < NSTG; it++) {
        const int i = tid + it*256;
        const int cp  = i / RC;
        const int col = i - cp*RC;
        const int gx  = x0 - 1 + col;
        float f0 = 0.f, f1 = 0.f;
        if (i < 16*RC && yok && (unsigned)gx < (unsigned)HW) {
            const float* p = xn + ((2*cp)*HW + gy)*HW + gx;
            f0 = p[0];
            f1 = p[HW*HW];
        }
        v0[it] = f0; v1[it] = f1;
    }
    #pragma unroll
    for (int it = 0; it < NSTG; it++) {
        const int i = tid + it*256;
        if (i < 16*RC) {
            const int cp  = i / RC;
            const int col = i - cp*RC;
            const __half2 h2 = __floats2half2_rn(v0[it], v1[it]);
            xs32[(slot*RC + col)*(CIP/2) + cp] = *reinterpret_cast<const uint32_t*>(&h2);
        }
    }
}

__global__ void __launch_bounds__(256, 2)
conv_mma(const float* __restrict__ x, float* __restrict__ out)
{
    extern __shared__ char smem[];
    uint32_t* xs32 = reinterpret_cast<uint32_t*>(smem + OFF_X);

    const int tid  = threadIdx.x;
    const int lane = tid & 31;
    const int w    = tid >> 5;
    const int n    = blockIdx.y;
    const int xt   = blockIdx.x % 3;
    const int st   = blockIdx.x / 3;            // 0..23
    const int x0   = xt * 128;
    const int row0 = st * 16;

    // ---- per-sample weights -> padded smem rows (vectorized u32) ----
    {
        const uint32_t* gw = reinterpret_cast<const uint32_t*>(g_w + (size_t)n*MODOUT);
        uint32_t* ws = reinterpret_cast<uint32_t*>(smem + OFF_W);
        for (int i = tid; i < COUT*(KDIM/2); i += 256) {
            const int co = i / 144, k2 = i - co*144;
            ws[co*(WST/2) + k2] = gw[i];
        }
    }
    const int lanehi = lane >> 2;
    const int laneq2 = (lane & 3) * 2;
    const float bias0 = g_bias[n*COUT + lanehi];
    const float bias1 = g_bias[n*COUT + lanehi + 8];
    const float bias2 = g_bias[n*COUT + lanehi + 16];
    const float bias3 = g_bias[n*COUT + lanehi + 24];

    const float* xn = x + (size_t)n * CIN * HW * HW;
    // prologue: stage rows row0-1 .. row0+4 (6 rows)
    stage_row(xn, xs32, row0 - 1, x0, tid);
    stage_row(xn, xs32, row0,     x0, tid);
    stage_row(xn, xs32, row0 + 1, x0, tid);
    stage_row(xn, xs32, row0 + 2, x0, tid);
    stage_row(xn, xs32, row0 + 3, x0, tid);
    stage_row(xn, xs32, row0 + 4, x0, tid);
    __syncthreads();

    const uint32_t sb   = smem_u32(smem);
    const uint32_t aoff = (uint32_t)(((lane & 15)*WST + (lane >> 4)*8) * 2);
    const uint32_t wbase = sb + OFF_W + aoff;
    const uint32_t xlane = sb + OFF_X +
        (uint32_t)(((w*16 + (lane & 7) + ((lane & 16) ? 8 : 0)) * CIP
                    + ((lane & 8) ? 8 : 0)) * 2);

    uint32_t aA[3][2][4];       // [kh buf][m-tile][regs]
    uint32_t bB[2][4];          // [buf][regs]

#define ALOADX(b, kh, kw, hf) do { \
    const uint32_t c32_ = (uint32_t)((((kh)*3+(kw))*2+(hf)) * 32u); \
    ldm4(aA[b][0], wbase + c32_); \
    ldm4(aA[b][1], wbase + c32_ + 16*WST*2); \
} while (0)

#define BLOADX(b, slot, kw, hf) do { \
    const uint32_t addr_ = xlane + \
        (uint32_t)(((((slot)*RC + (kw))*CIP) + (hf)*16) * 2); \
    ldm4(bB[b], addr_); \
} while (0)

#define MMA4(r, ab, bb) do { \
    mma_f16(acc[r][0][0], aA[ab][0], bB[bb]); \
    mma_f16(acc[r][1][0], aA[ab][1], bB[bb]); \
    mma_f16(acc[r][0][1], aA[ab][0], bB[bb]+2); \
    mma_f16(acc[r][1][1], aA[ab][1], bB[bb]+2); \
} while (0)

// Pipelined 4-row kwh body.
// Entry: aA[0]=kh0@(kw,hf), bB[0]=d-1@(kw,hf).
// Exit:  aA[0]=kh0@(nkw,nhf), bB[0]=d-1-next (@nslot, kw=nkw, hf=nhf).
#define KWH_BODY(kw, hf, nkw, nhf, nslot) do { \
    BLOADX(1, s_[1], kw, hf);        /* d0  */ \
    ALOADX(1, 1, kw, hf);            /* kh1 */ \
    MMA4(0, 0, 0);                   /* r0/kh0 @ d-1 */ \
    BLOADX(0, s_[2], kw, hf);        /* d1  */ \
    ALOADX(2, 2, kw, hf);            /* kh2 */ \
    MMA4(1, 0, 1);                   /* r1/kh0 @ d0 */ \
    MMA4(0, 1, 1);                   /* r0/kh1 @ d0 */ \
    BLOADX(1, s_[3], kw, hf);        /* d2  */ \
    MMA4(2, 0, 0);                   /* r2/kh0 @ d1 */ \
    MMA4(1, 1, 0);                   /* r1/kh1 @ d1 */ \
    MMA4(0, 2, 0);                   /* r0/kh2 @ d1 */ \
    BLOADX(0, s_[4], kw, hf);        /* d3  */ \
    MMA4(3, 0, 1);                   /* r3/kh0 @ d2 */ \
    MMA4(2, 1, 1);                   /* r2/kh1 @ d2 */ \
    MMA4(1, 2, 1);                   /* r1/kh2 @ d2 */ \
    BLOADX(1, s_[5], kw, hf);        /* d4  */ \
    ALOADX(0, 0, nkw, nhf);          /* next kh0 */ \
    MMA4(3, 1, 0);                   /* r3/kh1 @ d3 */ \
    MMA4(2, 2, 0);                   /* r2/kh2 @ d3 */ \
    BLOADX(0, nslot, nkw, nhf);      /* next d-1 */ \
    MMA4(3, 2, 1);                   /* r3/kh2 @ d4 */ \
} while (0)

    #pragma unroll 1
    for (int q = 0; q < 4; q++) {
        const int y = row0 + 4*q;
        int s_[6];
        #pragma unroll
        for (int dd = 0; dd < 6; dd++) s_[dd] = (y - 1 + dd) & (NSLOT - 1);

        float acc[4][2][2][4];
        #pragma unroll
        for (int r = 0; r < 4; r++)
            #pragma unroll
            for (int mi = 0; mi < 2; mi++)
                #pragma unroll
                for (int j = 0; j < 2; j++)
                    #pragma unroll
                    for (int qq = 0; qq < 4; qq++) acc[r][mi][j][qq] = 0.f;

        // quad prologue: kwh0 entry fragments
        ALOADX(0, 0, 0, 0);
        BLOADX(0, s_[0], 0, 0);

        KWH_BODY(0, 0, 0, 1, s_[0]);
        KWH_BODY(0, 1, 1, 0, s_[0]);
        KWH_BODY(1, 0, 1, 1, s_[0]);
        KWH_BODY(1, 1, 2, 0, s_[0]);
        KWH_BODY(2, 0, 2, 1, s_[0]);
        KWH_BODY(2, 1, 0, 0, s_[0]);   // tail loads unused (next quad reloads)

        // ---- epilogue: 4 rows, bias + coalesced float2 stores ----
        #pragma unroll
        for (int r = 0; r < 4; r++) {
            const int yy = y + r;
            const int pxb = x0 + w*16 + laneq2;
            #pragma unroll
            for (int mi = 0; mi < 2; mi++) {
                const float bA = mi ? bias2 : bias0;
                const float bB2 = mi ? bias3 : bias1;
                const int coA = mi*16 + lanehi;
                float* o0 = out + (((size_t)n*COUT + coA)*HW + yy)*HW + pxb;
                #pragma unroll
                for (int j = 0; j < 2; j++) {
                    *reinterpret_cast<float2*>(o0 + 8*j) =
                        make_float2(acc[r][mi][j][0] + bA, acc[r][mi][j][1] + bA);
                    *reinterpret_cast<float2*>(o0 + 8*j + (size_t)8*HW*HW) =
                        make_float2(acc[r][mi][j][2] + bB2, acc[r][mi][j][3] + bB2);
                }
            }
        }

        if (q < 3) {
            __syncthreads();
            stage_row(xn, xs32, y + 5, x0, tid);
            stage_row(xn, xs32, y + 6, x0, tid);
            stage_row(xn, xs32, y + 7, x0, tid);
            stage_row(xn, xs32, y + 8, x0, tid);
            __syncthreads();
        }
    }
#undef ALOADX
#undef BLOADX
#undef MMA4
#undef KWH_BODY
}

// ---------------------------------------------------------------------------
extern "C" void kernel_launch(void* const* d_in, const int* in_sizes, int n_in,
                              void* d_out, int out_size)
{
    const float* x      = (const float*)d_in[0];
    const float* y      = (const float*)d_in[1];
    const float* weight = (const float*)d_in[2];
    const float* fc_w1  = (const float*)d_in[3];
    const float* fc_b1  = (const float*)d_in[4];
    const float* fc_a   = (const float*)d_in[5];
    const float* fc_w2  = (const float*)d_in[6];
    const float* fc_b2  = (const float*)d_in[7];
    const float* b_w1   = (const float*)d_in[8];
    const float* b_b1   = (const float*)d_in[9];
    const float* b_a    = (const float*)d_in[10];
    const float* b_w2   = (const float*)d_in[11];
    const float* b_b2   = (const float*)d_in[12];
    float* out = (float*)d_out;

    cudaFuncSetAttribute(conv_mma,
                         cudaFuncAttributeMaxDynamicSharedMemorySize,
                         CONV_SMEM);

    mlp_hidden<<<32, 128>>>(y, fc_w1, fc_b1, fc_a, b_w1, b_b1, b_a);
    mlp_out<<<289, 512>>>(weight, fc_w2, fc_b2, b_w2, b_b2);
    conv_mma<<<dim3(72, BN), 256, CONV_SMEM>>>(x, out);
}

// round 14
// speedup vs baseline: 1.1067x; 1.1067x over previous
#include <cuda_runtime.h>
#include <cuda_fp16.h>
#include <math.h>
#include <stdint.h>

#define BN   8
#define CIN  32
#define COUT 32
#define HW   384
#define AUX  128
#define HID  256
#define MODOUT (COUT*CIN*9)   // 9216
#define KDIM 288              // k = tap*32 + ci
#define WST  296              // padded W row stride (conflict-free ldmatrix)

// Scratch (allocation-free rule: __device__ globals)
__device__ float g_bias[BN * COUT];
__device__ float g_h[BN * 2 * HID];        // [n][branch][HID]
__device__ __half g_w[BN * COUT * KDIM];   // [n][co][tap*32+ci] fp16

// ---------------------------------------------------------------------------
// warp-MMA helpers (sm_80-class, valid on compute_103 without 'a')
// ---------------------------------------------------------------------------
__device__ __forceinline__ uint32_t smem_u32(const void* p) {
    uint32_t a;
    asm("{ .reg .u64 t; cvta.to.shared.u64 t, %1; cvt.u32.u64 %0, t; }"
        : "=r"(a) : "l"(p));
    return a;
}
__device__ __forceinline__ void ldm4(uint32_t r[4], uint32_t addr) {
    asm volatile("ldmatrix.sync.aligned.m8n8.x4.shared.b16 {%0,%1,%2,%3}, [%4];"
        : "=r"(r[0]), "=r"(r[1]), "=r"(r[2]), "=r"(r[3]) : "r"(addr));
}
__device__ __forceinline__ void mma_f16(float d[4], const uint32_t a[4],
                                        const uint32_t b[2]) {
    asm volatile("mma.sync.aligned.m16n8k16.row.col.f32.f16.f16.f32 "
        "{%0,%1,%2,%3}, {%4,%5,%6,%7}, {%8,%9}, {%0,%1,%2,%3};"
        : "+f"(d[0]), "+f"(d[1]), "+f"(d[2]), "+f"(d[3])
        : "r"(a[0]), "r"(a[1]), "r"(a[2]), "r"(a[3]), "r"(b[0]), "r"(b[1]));
}

// ---------------------------------------------------------------------------
// MLP kernel 1: hidden layers. grid (8,2), block 512.
// Thread = (col 0..255, AUX-half 0..1); smem combine. Chain = 8 DRAM waves.
// ---------------------------------------------------------------------------
__global__ void mlp_hidden(const float* __restrict__ y,
                           const float* __restrict__ fc_w1, const float* __restrict__ fc_b1,
                           const float* __restrict__ fc_a_p,
                           const float* __restrict__ b_w1,  const float* __restrict__ b_b1,
                           const float* __restrict__ b_a_p)
{
    __shared__ float y_s[AUX];
    __shared__ float part[512];
    const int n  = blockIdx.x;
    const int br = blockIdx.y;
    const int t  = threadIdx.x;
    const int col = t & 255;
    const int hf  = t >> 8;

    if (t < AUX) y_s[t] = y[n*AUX + t];
    __syncthreads();

    const float* w1 = br ? b_w1 : fc_w1;
    const float* b1 = br ? b_b1 : fc_b1;
    const float  a  = br ? *b_a_p : *fc_a_p;
    const int i0 = hf * 64;

    float acc[8] = {0,0,0,0,0,0,0,0};
    #pragma unroll
    for (int i = 0; i < 64; i += 8) {
        #pragma unroll
        for (int q = 0; q < 8; q++)
            acc[q] = fmaf(y_s[i0+i+q], w1[(i0+i+q)*HID + col], acc[q]);
    }
    part[t] = ((acc[0]+acc[1])+(acc[2]+acc[3]))
            + ((acc[4]+acc[5])+(acc[6]+acc[7]));
    __syncthreads();

    if (t < 256) {
        const float h = part[t] + part[t+256] + b1[t];
        g_h[(n*2 + br)*HID + t] = (h >= 0.f) ? h : a*h;
    }
}

// ---------------------------------------------------------------------------
// MLP kernel 2: output layers. grid 289, block 1024.
// Mod blocks: 32 j x 8 samples x 4 HID-quarters; chain = 4 DRAM waves.
// Block 288: biases.
// ---------------------------------------------------------------------------
__global__ void mlp_out(const float* __restrict__ weight,
                        const float* __restrict__ fc_w2, const float* __restrict__ fc_b2,
                        const float* __restrict__ b_w2,  const float* __restrict__ b_b2)
{
    __shared__ float h_s[BN * HID];
    __shared__ float part[1024];
    const int t = threadIdx.x;

    if (blockIdx.x < 288) {
        #pragma unroll
        for (int i = t; i < BN*HID; i += 1024)
            h_s[i] = g_h[((i >> 8)*2)*HID + (i & 255)];
        __syncthreads();

        const int qt = t >> 8;              // HID quarter 0..3
        const int tt = t & 255;
        const int n  = tt >> 5;
        const int j  = blockIdx.x*32 + (tt & 31);
        const float* hp = h_s + n*HID + qt*64;
        const float* wp = fc_w2 + (size_t)(qt*64)*MODOUT + j;

        float m[8] = {0,0,0,0,0,0,0,0};
        #pragma unroll
        for (int hh = 0; hh < 64; hh += 8) {
            #pragma unroll
            for (int q = 0; q < 8; q++)
                m[q] = fmaf(hp[hh+q], wp[(size_t)(hh+q)*MODOUT], m[q]);
        }
        part[t] = ((m[0]+m[1])+(m[2]+m[3])) + ((m[4]+m[5])+(m[6]+m[7]));
        __syncthreads();

        if (t < 256) {
            const float mm = part[t] + part[t+256] + part[t+512] + part[t+768]
                           + fc_b2[j];
            const float sg = 1.f / (1.f + expf(-mm));
            const float wm = sg * weight[j];
            const int co  = j / 288;
            const int r   = j - co*288;
            const int ci  = r / 9;
            const int tap = r - ci*9;
            const int nn  = t >> 5;
            g_w[(nn*COUT + co)*KDIM + tap*32 + ci] = __float2half_rn(wm);
        }
    } else {
        #pragma unroll
        for (int i = t; i < BN*HID; i += 1024)
            h_s[i] = g_h[((i >> 8)*2 + 1)*HID + (i & 255)];
        __syncthreads();

        if (t < 256) {
            const int n  = t >> 5;
            const int co = t & 31;
            const float* hb = h_s + n*HID;
            float m[8] = {0,0,0,0,0,0,0,0};
            #pragma unroll
            for (int hh = 0; hh < HID; hh += 8) {
                #pragma unroll
                for (int q = 0; q < 8; q++)
                    m[q] = fmaf(hb[hh+q], b_w2[(hh+q)*COUT + co], m[q]);
            }
            g_bias[n*COUT + co] = ((m[0]+m[1])+(m[2]+m[3]))
                                + ((m[4]+m[5])+(m[6]+m[7])) + b_b2[co];
        }
    }
}

// ---------------------------------------------------------------------------
// Conv: mma.sync fp16 single-pass, 2-row blocking, 3 CTAs/SM,
// cross-kwh software pipeline (round-12 version — best measured).
// ---------------------------------------------------------------------------
#define RC       130
#define CIP      40
#define NSLOT    4
#define SLAB_B   (NSLOT*RC*CIP*2)          // 41600
#define W_BYTES  (COUT*WST*2)              // 18944
#define OFF_W    0
#define OFF_X    (W_BYTES)                 // 18944
#define CONV_SMEM (OFF_X + SLAB_B)         // 60544 -> 3 CTAs/SM
#define NSTG     9                         // ceil(16*RC/256)

__device__ __forceinline__ void stage_row(const float* __restrict__ xn,
                                          uint32_t* __restrict__ xs32,
                                          int gy, int x0, int tid)
{
    const int slot = (gy + NSLOT) & (NSLOT - 1);
    const bool yok = (unsigned)gy < (unsigned)HW;
    float v0[NSTG], v1[NSTG];
    #pragma unroll
    for (int it = 0; it < NSTG; it++) {
        const int i = tid + it*256;
        const int cp  = i / RC;
        const int col = i - cp*RC;
        const int gx  = x0 - 1 + col;
        float f0 = 0.f, f1 = 0.f;
        if (i < 16*RC && yok && (unsigned)gx < (unsigned)HW) {
            const float* p = xn + ((2*cp)*HW + gy)*HW + gx;
            f0 = p[0];
            f1 = p[HW*HW];
        }
        v0[it] = f0; v1[it] = f1;
    }
    #pragma unroll
    for (int it = 0; it < NSTG; it++) {
        const int i = tid + it*256;
        if (i < 16*RC) {
            const int cp  = i / RC;
            const int col = i - cp*RC;
            const __half2 h2 = __floats2half2_rn(v0[it], v1[it]);
            xs32[(slot*RC + col)*(CIP/2) + cp] = *reinterpret_cast<const uint32_t*>(&h2);
        }
    }
}

__global__ void __launch_bounds__(256, 3)
conv_mma(const float* __restrict__ x, float* __restrict__ out)
{
    extern __shared__ char smem[];
    uint32_t* xs32 = reinterpret_cast<uint32_t*>(smem + OFF_X);

    const int tid  = threadIdx.x;
    const int lane = tid & 31;
    const int w    = tid >> 5;
    const int n    = blockIdx.y;
    const int xt   = blockIdx.x % 3;
    const int st   = blockIdx.x / 3;            // 0..36
    const int x0   = xt * 128;
    const int row0  = (st < 7) ? st*12 : 84 + (st-7)*10;
    const int pairs = (st < 7) ? 6 : 5;

    // ---- per-sample weights -> padded smem rows (vectorized u32) ----
    {
        const uint32_t* gw = reinterpret_cast<const uint32_t*>(g_w + (size_t)n*MODOUT);
        uint32_t* ws = reinterpret_cast<uint32_t*>(smem + OFF_W);
        for (int i = tid; i < COUT*(KDIM/2); i += 256) {
            const int co = i / 144, k2 = i - co*144;
            ws[co*(WST/2) + k2] = gw[i];
        }
    }
    const int lanehi = lane >> 2;
    const int laneq2 = (lane & 3) * 2;
    const float bias0 = g_bias[n*COUT + lanehi];
    const float bias1 = g_bias[n*COUT + lanehi + 8];
    const float bias2 = g_bias[n*COUT + lanehi + 16];
    const float bias3 = g_bias[n*COUT + lanehi + 24];

    const float* xn = x + (size_t)n * CIN * HW * HW;
    stage_row(xn, xs32, row0 - 1, x0, tid);
    stage_row(xn, xs32, row0,     x0, tid);
    stage_row(xn, xs32, row0 + 1, x0, tid);
    stage_row(xn, xs32, row0 + 2, x0, tid);
    __syncthreads();

    const uint32_t sb   = smem_u32(smem);
    const uint32_t aoff = (uint32_t)(((lane & 15)*WST + (lane >> 4)*8) * 2);
    const uint32_t wbase = sb + OFF_W + aoff;
    const uint32_t xlane = sb + OFF_X +
        (uint32_t)(((w*16 + (lane & 7) + ((lane & 16) ? 8 : 0)) * CIP
                    + ((lane & 8) ? 8 : 0)) * 2);

    uint32_t aA[2][2][4];       // [buf][m-tile][regs]
    uint32_t bB[2][4];          // [buf][regs]: j0 = +0, j1 = +2

#define ALOADX(b, kh, kw, hf) do { \
    const uint32_t c32_ = (uint32_t)(((((kh)*3+(kw))*2+(hf))) * 32u); \
    ldm4(aA[b][0], wbase + c32_); \
    ldm4(aA[b][1], wbase + c32_ + 16*WST*2); \
} while (0)

#define BLOADX(b, slot, kw, hf) do { \
    const uint32_t addr_ = xlane + \
        (uint32_t)(((((slot)*RC + (kw))*CIP) + (hf)*16) * 2); \
    ldm4(bB[b], addr_); \
} while (0)

#define MMA4(r, ab, bb) do { \
    mma_f16(acc[r][0][0], aA[ab][0], bB[bb]); \
    mma_f16(acc[r][1][0], aA[ab][1], bB[bb]); \
    mma_f16(acc[r][0][1], aA[ab][0], bB[bb]+2); \
    mma_f16(acc[r][1][1], aA[ab][1], bB[bb]+2); \
} while (0)

// Pipelined kwh body. Entry: aA[ain]=kh0@(kw,hf), bB[0]=d0@(kw,hf).
// Exit: aA[aot]=kh0@(nkw,nhf), bB[0]=d0-next (@nslot).
#define KWH_BODY(ain, aot, kw, hf, nkw, nhf, nslot) do { \
    BLOADX(1, s_[1], kw, hf);        /* d1 */ \
    ALOADX(aot, 1, kw, hf);          /* kh1 */ \
    MMA4(0, ain, 0);                 /* row0/kh0 @ d0 */ \
    BLOADX(0, s_[2], kw, hf);        /* d2 */ \
    MMA4(1, ain, 1);                 /* row1/kh0 @ d1 */ \
    ALOADX(ain, 2, kw, hf);          /* kh2 */ \
    MMA4(0, aot, 1);                 /* row0/kh1 @ d1 */ \
    BLOADX(1, s_[3], kw, hf);        /* d3 */ \
    MMA4(1, aot, 0);                 /* row1/kh1 @ d2 */ \
    ALOADX(aot, 0, nkw, nhf);        /* next kh0 */ \
    MMA4(0, ain, 0);                 /* row0/kh2 @ d2 */ \
    BLOADX(0, nslot, nkw, nhf);      /* next d0 */ \
    MMA4(1, ain, 1);                 /* row1/kh2 @ d3 */ \
} while (0)

    // strip prologue: first pair's kwh0 entry fragments
    ALOADX(0, 0, 0, 0);
    BLOADX(0, (row0 - 1) & (NSLOT - 1), 0, 0);

    #pragma unroll 1
    for (int t = 0; t < pairs; t++) {
        const int y = row0 + 2*t;
        int s_[4];
        #pragma unroll
        for (int dd = 0; dd < 4; dd++) s_[dd] = (y - 1 + dd) & (NSLOT - 1);

        float acc[2][2][2][4];
        #pragma unroll
        for (int r = 0; r < 2; r++)
            #pragma unroll
            for (int mi = 0; mi < 2; mi++)
                #pragma unroll
                for (int j = 0; j < 2; j++)
                    #pragma unroll
                    for (int q = 0; q < 4; q++) acc[r][mi][j][q] = 0.f;

        // 6 kwh bodies, A-buffer parity alternating; kwh5 tail preloads
        // next pair's kwh0 fragments (next d0 slot = s_[2] = (y+1)&3).
        KWH_BODY(0, 1, 0, 0, 0, 1, s_[0]);
        KWH_BODY(1, 0, 0, 1, 1, 0, s_[0]);
        KWH_BODY(0, 1, 1, 0, 1, 1, s_[0]);
        KWH_BODY(1, 0, 1, 1, 2, 0, s_[0]);
        KWH_BODY(0, 1, 2, 0, 2, 1, s_[0]);
        KWH_BODY(1, 0, 2, 1, 0, 0, s_[2]);

        // ---- epilogue: 2 rows, bias + coalesced float2 stores ----
        #pragma unroll
        for (int r = 0; r < 2; r++) {
            const int yy = y + r;
            const int pxb = x0 + w*16 + laneq2;
            #pragma unroll
            for (int mi = 0; mi < 2; mi++) {
                const float bA = mi ? bias2 : bias0;
                const float bB2 = mi ? bias3 : bias1;
                const int coA = mi*16 + lanehi;
                float* o0 = out + (((size_t)n*COUT + coA)*HW + yy)*HW + pxb;
                #pragma unroll
                for (int j = 0; j < 2; j++) {
                    *reinterpret_cast<float2*>(o0 + 8*j) =
                        make_float2(acc[r][mi][j][0] + bA, acc[r][mi][j][1] + bA);
                    *reinterpret_cast<float2*>(o0 + 8*j + (size_t)8*HW*HW) =
                        make_float2(acc[r][mi][j][2] + bB2, acc[r][mi][j][3] + bB2);
                }
            }
        }

        if (t + 1 < pairs) {
            __syncthreads();
            stage_row(xn, xs32, y + 3, x0, tid);
            stage_row(xn, xs32, y + 4, x0, tid);
            __syncthreads();
        }
    }
#undef ALOADX
#undef BLOADX
#undef MMA4
#undef KWH_BODY
}

// ---------------------------------------------------------------------------
extern "C" void kernel_launch(void* const* d_in, const int* in_sizes, int n_in,
                              void* d_out, int out_size)
{
    const float* x      = (const float*)d_in[0];
    const float* y      = (const float*)d_in[1];
    const float* weight = (const float*)d_in[2];
    const float* fc_w1  = (const float*)d_in[3];
    const float* fc_b1  = (const float*)d_in[4];
    const float* fc_a   = (const float*)d_in[5];
    const float* fc_w2  = (const float*)d_in[6];
    const float* fc_b2  = (const float*)d_in[7];
    const float* b_w1   = (const float*)d_in[8];
    const float* b_b1   = (const float*)d_in[9];
    const float* b_a    = (const float*)d_in[10];
    const float* b_w2   = (const float*)d_in[11];
    const float* b_b2   = (const float*)d_in[12];
    float* out = (float*)d_out;

    cudaFuncSetAttribute(conv_mma,
                         cudaFuncAttributeMaxDynamicSharedMemorySize,
                         CONV_SMEM);

    mlp_hidden<<<dim3(BN, 2), 512>>>(y, fc_w1, fc_b1, fc_a, b_w1, b_b1, b_a);
    mlp_out<<<289, 1024>>>(weight, fc_w2, fc_b2, b_w2, b_b2);
    conv_mma<<<dim3(111, BN), 256, CONV_SMEM>>>(x, out);
}

// round 15
// speedup vs baseline: 1.1462x; 1.0357x over previous
#include <cuda_runtime.h>
#include <cuda_fp16.h>
#include <math.h>
#include <stdint.h>

#define BN   8
#define CIN  32
#define COUT 32
#define HW   384
#define AUX  128
#define HID  256
#define MODOUT (COUT*CIN*9)   // 9216
#define KDIM 288              // k = tap*32 + ci
#define WST  296              // padded W row stride (conflict-free ldmatrix)

// Scratch (allocation-free rule: __device__ globals)
__device__ float g_bias[BN * COUT];
__device__ float g_h[BN * 2 * HID];        // [n][branch][HID]
__device__ __half g_w[BN * COUT * KDIM];   // [n][co][tap*32+ci] fp16

// ---------------------------------------------------------------------------
// warp-MMA helpers (sm_80-class, valid on compute_103 without 'a')
// ---------------------------------------------------------------------------
__device__ __forceinline__ uint32_t smem_u32(const void* p) {
    uint32_t a;
    asm("{ .reg .u64 t; cvta.to.shared.u64 t, %1; cvt.u32.u64 %0, t; }"
        : "=r"(a) : "l"(p));
    return a;
}
__device__ __forceinline__ void ldm4(uint32_t r[4], uint32_t addr) {
    asm volatile("ldmatrix.sync.aligned.m8n8.x4.shared.b16 {%0,%1,%2,%3}, [%4];"
        : "=r"(r[0]), "=r"(r[1]), "=r"(r[2]), "=r"(r[3]) : "r"(addr));
}
__device__ __forceinline__ void mma_f16(float d[4], const uint32_t a[4],
                                        const uint32_t b[2]) {
    asm volatile("mma.sync.aligned.m16n8k16.row.col.f32.f16.f16.f32 "
        "{%0,%1,%2,%3}, {%4,%5,%6,%7}, {%8,%9}, {%0,%1,%2,%3};"
        : "+f"(d[0]), "+f"(d[1]), "+f"(d[2]), "+f"(d[3])
        : "r"(a[0]), "r"(a[1]), "r"(a[2]), "r"(a[3]), "r"(b[0]), "r"(b[1]));
}

// ---------------------------------------------------------------------------
// MLP kernel 1: hidden layers. grid (8,2), block 512 (r14 version, 7.8us).
// Thread = (col 0..255, AUX-half 0..1); smem combine.
// ---------------------------------------------------------------------------
__global__ void mlp_hidden(const float* __restrict__ y,
                           const float* __restrict__ fc_w1, const float* __restrict__ fc_b1,
                           const float* __restrict__ fc_a_p,
                           const float* __restrict__ b_w1,  const float* __restrict__ b_b1,
                           const float* __restrict__ b_a_p)
{
    __shared__ float y_s[AUX];
    __shared__ float part[512];
    const int n  = blockIdx.x;
    const int br = blockIdx.y;
    const int t  = threadIdx.x;
    const int col = t & 255;
    const int hf  = t >> 8;

    if (t < AUX) y_s[t] = y[n*AUX + t];
    __syncthreads();

    const float* w1 = br ? b_w1 : fc_w1;
    const float* b1 = br ? b_b1 : fc_b1;
    const float  a  = br ? *b_a_p : *fc_a_p;
    const int i0 = hf * 64;

    float acc[8] = {0,0,0,0,0,0,0,0};
    #pragma unroll
    for (int i = 0; i < 64; i += 8) {
        #pragma unroll
        for (int q = 0; q < 8; q++)
            acc[q] = fmaf(y_s[i0+i+q], w1[(i0+i+q)*HID + col], acc[q]);
    }
    part[t] = ((acc[0]+acc[1])+(acc[2]+acc[3]))
            + ((acc[4]+acc[5])+(acc[6]+acc[7]));
    __syncthreads();

    if (t < 256) {
        const float h = part[t] + part[t+256] + b1[t];
        g_h[(n*2 + br)*HID + t] = (h >= 0.f) ? h : a*h;
    }
}

// ---------------------------------------------------------------------------
// MLP kernel 2: output layers. grid 289, block 512, ILP-16 (r12 version).
// ---------------------------------------------------------------------------
__global__ void mlp_out(const float* __restrict__ weight,
                        const float* __restrict__ fc_w2, const float* __restrict__ fc_b2,
                        const float* __restrict__ b_w2,  const float* __restrict__ b_b2)
{
    __shared__ float h_s[BN * HID];
    __shared__ float part[512];
    const int t = threadIdx.x;

    if (blockIdx.x < 288) {
        #pragma unroll
        for (int i = t; i < BN*HID; i += 512)
            h_s[i] = g_h[((i >> 8)*2)*HID + (i & 255)];
        __syncthreads();

        const int hf = t >> 8;              // HID half
        const int tt = t & 255;
        const int n  = tt >> 5;
        const int j  = blockIdx.x*32 + (tt & 31);
        const float* hp = h_s + n*HID + hf*128;
        const float* wp = fc_w2 + (size_t)(hf*128)*MODOUT + j;

        float m[16];
        #pragma unroll
        for (int q = 0; q < 16; q++) m[q] = 0.f;
        #pragma unroll
        for (int hh = 0; hh < 128; hh += 16) {
            #pragma unroll
            for (int q = 0; q < 16; q++)
                m[q] = fmaf(hp[hh+q], wp[(size_t)(hh+q)*MODOUT], m[q]);
        }
        float s = 0.f;
        #pragma unroll
        for (int q = 0; q < 16; q++) s += m[q];
        part[t] = s;
        __syncthreads();

        if (t < 256) {
            const float mm = part[t] + part[t+256] + fc_b2[j];
            const float sg = 1.f / (1.f + expf(-mm));
            const float wm = sg * weight[j];
            const int co  = j / 288;
            const int r   = j - co*288;
            const int ci  = r / 9;
            const int tap = r - ci*9;
            const int nn  = t >> 5;
            g_w[(nn*COUT + co)*KDIM + tap*32 + ci] = __float2half_rn(wm);
        }
    } else {
        #pragma unroll
        for (int i = t; i < BN*HID; i += 512)
            h_s[i] = g_h[((i >> 8)*2 + 1)*HID + (i & 255)];
        __syncthreads();

        if (t < 256) {
            const int n  = t >> 5;
            const int co = t & 31;
            const float* hb = h_s + n*HID;
            float m[8];
            #pragma unroll
            for (int q = 0; q < 8; q++) m[q] = 0.f;
            #pragma unroll
            for (int hh = 0; hh < HID; hh += 8) {
                #pragma unroll
                for (int q = 0; q < 8; q++)
                    m[q] = fmaf(hb[hh+q], b_w2[(hh+q)*COUT + co], m[q]);
            }
            float s = 0.f;
            #pragma unroll
            for (int q = 0; q < 8; q++) s += m[q];
            g_bias[n*COUT + co] = s + b_b2[co];
        }
    }
}

// ---------------------------------------------------------------------------
// Conv: mma.sync fp16 single-pass, 2-row blocking, 3 CTAs/SM,
// cross-kwh software pipeline (round-12 version — best measured ~99us).
// ---------------------------------------------------------------------------
#define RC       130
#define CIP      40
#define NSLOT    4
#define SLAB_B   (NSLOT*RC*CIP*2)          // 41600
#define W_BYTES  (COUT*WST*2)              // 18944
#define OFF_W    0
#define OFF_X    (W_BYTES)                 // 18944
#define CONV_SMEM (OFF_X + SLAB_B)         // 60544 -> 3 CTAs/SM
#define NSTG     9                         // ceil(16*RC/256)

__device__ __forceinline__ void stage_row(const float* __restrict__ xn,
                                          uint32_t* __restrict__ xs32,
                                          int gy, int x0, int tid)
{
    const int slot = (gy + NSLOT) & (NSLOT - 1);
    const bool yok = (unsigned)gy < (unsigned)HW;
    float v0[NSTG], v1[NSTG];
    #pragma unroll
    for (int it = 0; it < NSTG; it++) {
        const int i = tid + it*256;
        const int cp  = i / RC;
        const int col = i - cp*RC;
        const int gx  = x0 - 1 + col;
        float f0 = 0.f, f1 = 0.f;
        if (i < 16*RC && yok && (unsigned)gx < (unsigned)HW) {
            const float* p = xn + ((2*cp)*HW + gy)*HW + gx;
            f0 = p[0];
            f1 = p[HW*HW];
        }
        v0[it] = f0; v1[it] = f1;
    }
    #pragma unroll
    for (int it = 0; it < NSTG; it++) {
        const int i = tid + it*256;
        if (i < 16*RC) {
            const int cp  = i / RC;
            const int col = i - cp*RC;
            const __half2 h2 = __floats2half2_rn(v0[it], v1[it]);
            xs32[(slot*RC + col)*(CIP/2) + cp] = *reinterpret_cast<const uint32_t*>(&h2);
        }
    }
}

__global__ void __launch_bounds__(256, 3)
conv_mma(const float* __restrict__ x, float* __restrict__ out)
{
    extern __shared__ char smem[];
    uint32_t* xs32 = reinterpret_cast<uint32_t*>(smem + OFF_X);

    const int tid  = threadIdx.x;
    const int lane = tid & 31;
    const int w    = tid >> 5;
    const int n    = blockIdx.y;
    const int xt   = blockIdx.x % 3;
    const int st   = blockIdx.x / 3;            // 0..36
    const int x0   = xt * 128;
    const int row0  = (st < 7) ? st*12 : 84 + (st-7)*10;
    const int pairs = (st < 7) ? 6 : 5;

    // ---- per-sample weights -> padded smem rows (vectorized u32) ----
    {
        const uint32_t* gw = reinterpret_cast<const uint32_t*>(g_w + (size_t)n*MODOUT);
        uint32_t* ws = reinterpret_cast<uint32_t*>(smem + OFF_W);
        for (int i = tid; i < COUT*(KDIM/2); i += 256) {
            const int co = i / 144, k2 = i - co*144;
            ws[co*(WST/2) + k2] = gw[i];
        }
    }
    const int lanehi = lane >> 2;
    const int laneq2 = (lane & 3) * 2;
    const float bias0 = g_bias[n*COUT + lanehi];
    const float bias1 = g_bias[n*COUT + lanehi + 8];
    const float bias2 = g_bias[n*COUT + lanehi + 16];
    const float bias3 = g_bias[n*COUT + lanehi + 24];

    const float* xn = x + (size_t)n * CIN * HW * HW;
    stage_row(xn, xs32, row0 - 1, x0, tid);
    stage_row(xn, xs32, row0,     x0, tid);
    stage_row(xn, xs32, row0 + 1, x0, tid);
    stage_row(xn, xs32, row0 + 2, x0, tid);
    __syncthreads();

    const uint32_t sb   = smem_u32(smem);
    const uint32_t aoff = (uint32_t)(((lane & 15)*WST + (lane >> 4)*8) * 2);
    const uint32_t wbase = sb + OFF_W + aoff;
    const uint32_t xlane = sb + OFF_X +
        (uint32_t)(((w*16 + (lane & 7) + ((lane & 16) ? 8 : 0)) * CIP
                    + ((lane & 8) ? 8 : 0)) * 2);

    uint32_t aA[2][2][4];       // [buf][m-tile][regs]
    uint32_t bB[2][4];          // [buf][regs]: j0 = +0, j1 = +2

#define ALOADX(b, kh, kw, hf) do { \
    const uint32_t c32_ = (uint32_t)(((((kh)*3+(kw))*2+(hf))) * 32u); \
    ldm4(aA[b][0], wbase + c32_); \
    ldm4(aA[b][1], wbase + c32_ + 16*WST*2); \
} while (0)

#define BLOADX(b, slot, kw, hf) do { \
    const uint32_t addr_ = xlane + \
        (uint32_t)(((((slot)*RC + (kw))*CIP) + (hf)*16) * 2); \
    ldm4(bB[b], addr_); \
} while (0)

#define MMA4(r, ab, bb) do { \
    mma_f16(acc[r][0][0], aA[ab][0], bB[bb]); \
    mma_f16(acc[r][1][0], aA[ab][1], bB[bb]); \
    mma_f16(acc[r][0][1], aA[ab][0], bB[bb]+2); \
    mma_f16(acc[r][1][1], aA[ab][1], bB[bb]+2); \
} while (0)

// Pipelined kwh body. Entry: aA[ain]=kh0@(kw,hf), bB[0]=d0@(kw,hf).
// Exit: aA[aot]=kh0@(nkw,nhf), bB[0]=d0-next (@nslot).
#define KWH_BODY(ain, aot, kw, hf, nkw, nhf, nslot) do { \
    BLOADX(1, s_[1], kw, hf);        /* d1 */ \
    ALOADX(aot, 1, kw, hf);          /* kh1 */ \
    MMA4(0, ain, 0);                 /* row0/kh0 @ d0 */ \
    BLOADX(0, s_[2], kw, hf);        /* d2 */ \
    MMA4(1, ain, 1);                 /* row1/kh0 @ d1 */ \
    ALOADX(ain, 2, kw, hf);          /* kh2 */ \
    MMA4(0, aot, 1);                 /* row0/kh1 @ d1 */ \
    BLOADX(1, s_[3], kw, hf);        /* d3 */ \
    MMA4(1, aot, 0);                 /* row1/kh1 @ d2 */ \
    ALOADX(aot, 0, nkw, nhf);        /* next kh0 */ \
    MMA4(0, ain, 0);                 /* row0/kh2 @ d2 */ \
    BLOADX(0, nslot, nkw, nhf);      /* next d0 */ \
    MMA4(1, ain, 1);                 /* row1/kh2 @ d3 */ \
} while (0)

    // strip prologue: first pair's kwh0 entry fragments
    ALOADX(0, 0, 0, 0);
    BLOADX(0, (row0 - 1) & (NSLOT - 1), 0, 0);

    #pragma unroll 1
    for (int t = 0; t < pairs; t++) {
        const int y = row0 + 2*t;
        int s_[4];
        #pragma unroll
        for (int dd = 0; dd < 4; dd++) s_[dd] = (y - 1 + dd) & (NSLOT - 1);

        float acc[2][2][2][4];
        #pragma unroll
        for (int r = 0; r < 2; r++)
            #pragma unroll
            for (int mi = 0; mi < 2; mi++)
                #pragma unroll
                for (int j = 0; j < 2; j++)
                    #pragma unroll
                    for (int q = 0; q < 4; q++) acc[r][mi][j][q] = 0.f;

        // 6 kwh bodies, A-buffer parity alternating; kwh5 tail preloads
        // next pair's kwh0 fragments (next d0 slot = s_[2] = (y+1)&3).
        KWH_BODY(0, 1, 0, 0, 0, 1, s_[0]);
        KWH_BODY(1, 0, 0, 1, 1, 0, s_[0]);
        KWH_BODY(0, 1, 1, 0, 1, 1, s_[0]);
        KWH_BODY(1, 0, 1, 1, 2, 0, s_[0]);
        KWH_BODY(0, 1, 2, 0, 2, 1, s_[0]);
        KWH_BODY(1, 0, 2, 1, 0, 0, s_[2]);

        // ---- epilogue: 2 rows, bias + coalesced float2 stores ----
        #pragma unroll
        for (int r = 0; r < 2; r++) {
            const int yy = y + r;
            const int pxb = x0 + w*16 + laneq2;
            #pragma unroll
            for (int mi = 0; mi < 2; mi++) {
                const float bA = mi ? bias2 : bias0;
                const float bB2 = mi ? bias3 : bias1;
                const int coA = mi*16 + lanehi;
                float* o0 = out + (((size_t)n*COUT + coA)*HW + yy)*HW + pxb;
                #pragma unroll
                for (int j = 0; j < 2; j++) {
                    *reinterpret_cast<float2*>(o0 + 8*j) =
                        make_float2(acc[r][mi][j][0] + bA, acc[r][mi][j][1] + bA);
                    *reinterpret_cast<float2*>(o0 + 8*j + (size_t)8*HW*HW) =
                        make_float2(acc[r][mi][j][2] + bB2, acc[r][mi][j][3] + bB2);
                }
            }
        }

        if (t + 1 < pairs) {
            __syncthreads();
            stage_row(xn, xs32, y + 3, x0, tid);
            stage_row(xn, xs32, y + 4, x0, tid);
            __syncthreads();
        }
    }
#undef ALOADX
#undef BLOADX
#undef MMA4
#undef KWH_BODY
}

// ---------------------------------------------------------------------------
extern "C" void kernel_launch(void* const* d_in, const int* in_sizes, int n_in,
                              void* d_out, int out_size)
{
    const float* x      = (const float*)d_in[0];
    const float* y      = (const float*)d_in[1];
    const float* weight = (const float*)d_in[2];
    const float* fc_w1  = (const float*)d_in[3];
    const float* fc_b1  = (const float*)d_in[4];
    const float* fc_a   = (const float*)d_in[5];
    const float* fc_w2  = (const float*)d_in[6];
    const float* fc_b2  = (const float*)d_in[7];
    const float* b_w1   = (const float*)d_in[8];
    const float* b_b1   = (const float*)d_in[9];
    const float* b_a    = (const float*)d_in[10];
    const float* b_w2   = (const float*)d_in[11];
    const float* b_b2   = (const float*)d_in[12];
    float* out = (float*)d_out;

    cudaFuncSetAttribute(conv_mma,
                         cudaFuncAttributeMaxDynamicSharedMemorySize,
                         CONV_SMEM);

    mlp_hidden<<<dim3(BN, 2), 512>>>(y, fc_w1, fc_b1, fc_a, b_w1, b_b1, b_a);
    mlp_out<<<289, 512>>>(weight, fc_w2, fc_b2, b_w2, b_b2);
    conv_mma<<<dim3(111, BN), 256, CONV_SMEM>>>(x, out);
}

// round 16
// speedup vs baseline: 1.1623x; 1.0141x over previous
#include <cuda_runtime.h>
#include <cuda_fp16.h>
#include <math.h>
#include <stdint.h>

#define BN   8
#define CIN  32
#define COUT 32
#define HW   384
#define AUX  128
#define HID  256
#define MODOUT (COUT*CIN*9)   // 9216
#define KDIM 288              // k = tap*32 + ci
#define WST  296              // padded W row stride (conflict-free ldmatrix)

// Scratch (allocation-free rule: __device__ globals)
__device__ float g_bias[BN * COUT];
__device__ float g_h[BN * 2 * HID];        // [n][branch][HID]
__device__ __half g_w[BN * COUT * KDIM];   // [n][co][tap*32+ci] fp16

// ---------------------------------------------------------------------------
// warp-MMA helpers (sm_80-class, valid on compute_103 without 'a')
// ---------------------------------------------------------------------------
__device__ __forceinline__ uint32_t smem_u32(const void* p) {
    uint32_t a;
    asm("{ .reg .u64 t; cvta.to.shared.u64 t, %1; cvt.u32.u64 %0, t; }"
        : "=r"(a) : "l"(p));
    return a;
}
__device__ __forceinline__ void ldm4(uint32_t r[4], uint32_t addr) {
    asm volatile("ldmatrix.sync.aligned.m8n8.x4.shared.b16 {%0,%1,%2,%3}, [%4];"
        : "=r"(r[0]), "=r"(r[1]), "=r"(r[2]), "=r"(r[3]) : "r"(addr));
}
__device__ __forceinline__ void mma_f16(float d[4], const uint32_t a[4],
                                        const uint32_t b[2]) {
    asm volatile("mma.sync.aligned.m16n8k16.row.col.f32.f16.f16.f32 "
        "{%0,%1,%2,%3}, {%4,%5,%6,%7}, {%8,%9}, {%0,%1,%2,%3};"
        : "+f"(d[0]), "+f"(d[1]), "+f"(d[2]), "+f"(d[3])
        : "r"(a[0]), "r"(a[1]), "r"(a[2]), "r"(a[3]), "r"(b[0]), "r"(b[1]));
}

// ---------------------------------------------------------------------------
// MLP kernel 1: hidden layers. grid (8,2), block 512 (measured 7.8us).
// ---------------------------------------------------------------------------
__global__ void mlp_hidden(const float* __restrict__ y,
                           const float* __restrict__ fc_w1, const float* __restrict__ fc_b1,
                           const float* __restrict__ fc_a_p,
                           const float* __restrict__ b_w1,  const float* __restrict__ b_b1,
                           const float* __restrict__ b_a_p)
{
    __shared__ float y_s[AUX];
    __shared__ float part[512];
    const int n  = blockIdx.x;
    const int br = blockIdx.y;
    const int t  = threadIdx.x;
    const int col = t & 255;
    const int hf  = t >> 8;

    if (t < AUX) y_s[t] = y[n*AUX + t];
    __syncthreads();

    const float* w1 = br ? b_w1 : fc_w1;
    const float* b1 = br ? b_b1 : fc_b1;
    const float  a  = br ? *b_a_p : *fc_a_p;
    const int i0 = hf * 64;

    float acc[8] = {0,0,0,0,0,0,0,0};
    #pragma unroll
    for (int i = 0; i < 64; i += 8) {
        #pragma unroll
        for (int q = 0; q < 8; q++)
            acc[q] = fmaf(y_s[i0+i+q], w1[(i0+i+q)*HID + col], acc[q]);
    }
    part[t] = ((acc[0]+acc[1])+(acc[2]+acc[3]))
            + ((acc[4]+acc[5])+(acc[6]+acc[7]));
    __syncthreads();

    if (t < 256) {
        const float h = part[t] + part[t+256] + b1[t];
        g_h[(n*2 + br)*HID + t] = (h >= 0.f) ? h : a*h;
    }
}

// ---------------------------------------------------------------------------
// MLP kernel 2: output layers. grid 577, block 512.
// Mod blocks 0..575: 16 j x 8 samples x 4 HID-quarters (chain = 4 DRAM waves).
// Block 576: biases. All blocks trigger PDL dependents launch at entry.
// ---------------------------------------------------------------------------
__global__ void mlp_out(const float* __restrict__ weight,
                        const float* __restrict__ fc_w2, const float* __restrict__ fc_b2,
                        const float* __restrict__ b_w2,  const float* __restrict__ b_b2)
{
    // allow the (PDL-launched) conv kernel to begin its independent prologue
    asm volatile("griddepcontrol.launch_dependents;");

    __shared__ float h_s[BN * HID];
    __shared__ float part[512];
    const int t = threadIdx.x;

    if (blockIdx.x < 576) {
        #pragma unroll
        for (int i = t; i < BN*HID; i += 512)
            h_s[i] = g_h[((i >> 8)*2)*HID + (i & 255)];
        __syncthreads();

        const int qt = t >> 7;              // HID quarter 0..3
        const int tt = t & 127;
        const int n  = tt >> 4;
        const int j  = blockIdx.x*16 + (tt & 15);
        const float* hp = h_s + n*HID + qt*64;
        const float* wp = fc_w2 + (size_t)(qt*64)*MODOUT + j;

        float m[16];
        #pragma unroll
        for (int q = 0; q < 16; q++) m[q] = 0.f;
        #pragma unroll
        for (int hh = 0; hh < 64; hh += 16) {
            #pragma unroll
            for (int q = 0; q < 16; q++)
                m[q] = fmaf(hp[hh+q], wp[(size_t)(hh+q)*MODOUT], m[q]);
        }
        float s = 0.f;
        #pragma unroll
        for (int q = 0; q < 16; q++) s += m[q];
        part[t] = s;
        __syncthreads();

        if (t < 128) {
            const int n2 = t >> 4;
            const int j2 = blockIdx.x*16 + (t & 15);
            const float mm = part[t] + part[t+128] + part[t+256] + part[t+384]
                           + fc_b2[j2];
            const float sg = 1.f / (1.f + expf(-mm));
            const float wm = sg * weight[j2];
            const int co  = j2 / 288;
            const int r   = j2 - co*288;
            const int ci  = r / 9;
            const int tap = r - ci*9;
            g_w[(n2*COUT + co)*KDIM + tap*32 + ci] = __float2half_rn(wm);
        }
    } else {
        #pragma unroll
        for (int i = t; i < BN*HID; i += 512)
            h_s[i] = g_h[((i >> 8)*2 + 1)*HID + (i & 255)];
        __syncthreads();

        if (t < 256) {
            const int n  = t >> 5;
            const int co = t & 31;
            const float* hb = h_s + n*HID;
            float m[8];
            #pragma unroll
            for (int q = 0; q < 8; q++) m[q] = 0.f;
            #pragma unroll
            for (int hh = 0; hh < HID; hh += 8) {
                #pragma unroll
                for (int q = 0; q < 8; q++)
                    m[q] = fmaf(hb[hh+q], b_w2[(hh+q)*COUT + co], m[q]);
            }
            float s = 0.f;
            #pragma unroll
            for (int q = 0; q < 8; q++) s += m[q];
            g_bias[n*COUT + co] = s + b_b2[co];
        }
    }
}

// ---------------------------------------------------------------------------
// Conv: mma.sync fp16 single-pass, 2-row blocking, 3 CTAs/SM,
// cross-kwh software pipeline (round-12 compute, unchanged) + PDL:
// input staging happens BEFORE griddepcontrol.wait (overlaps mlp_out);
// weights/bias (mlp_out products) are read only after the wait.
// ---------------------------------------------------------------------------
#define RC       130
#define CIP      40
#define NSLOT    4
#define SLAB_B   (NSLOT*RC*CIP*2)          // 41600
#define W_BYTES  (COUT*WST*2)              // 18944
#define OFF_W    0
#define OFF_X    (W_BYTES)                 // 18944
#define CONV_SMEM (OFF_X + SLAB_B)         // 60544 -> 3 CTAs/SM
#define NSTG     9                         // ceil(16*RC/256)

__device__ __forceinline__ void stage_row(const float* __restrict__ xn,
                                          uint32_t* __restrict__ xs32,
                                          int gy, int x0, int tid)
{
    const int slot = (gy + NSLOT) & (NSLOT - 1);
    const bool yok = (unsigned)gy < (unsigned)HW;
    float v0[NSTG], v1[NSTG];
    #pragma unroll
    for (int it = 0; it < NSTG; it++) {
        const int i = tid + it*256;
        const int cp  = i / RC;
        const int col = i - cp*RC;
        const int gx  = x0 - 1 + col;
        float f0 = 0.f, f1 = 0.f;
        if (i < 16*RC && yok && (unsigned)gx < (unsigned)HW) {
            const float* p = xn + ((2*cp)*HW + gy)*HW + gx;
            f0 = p[0];
            f1 = p[HW*HW];
        }
        v0[it] = f0; v1[it] = f1;
    }
    #pragma unroll
    for (int it = 0; it < NSTG; it++) {
        const int i = tid + it*256;
        if (i < 16*RC) {
            const int cp  = i / RC;
            const int col = i - cp*RC;
            const __half2 h2 = __floats2half2_rn(v0[it], v1[it]);
            xs32[(slot*RC + col)*(CIP/2) + cp] = *reinterpret_cast<const uint32_t*>(&h2);
        }
    }
}

__global__ void __launch_bounds__(256, 3)
conv_mma(const float* __restrict__ x, float* __restrict__ out)
{
    extern __shared__ char smem[];
    uint32_t* xs32 = reinterpret_cast<uint32_t*>(smem + OFF_X);

    const int tid  = threadIdx.x;
    const int lane = tid & 31;
    const int w    = tid >> 5;
    const int n    = blockIdx.y;
    const int xt   = blockIdx.x % 3;
    const int st   = blockIdx.x / 3;            // 0..36
    const int x0   = xt * 128;
    const int row0  = (st < 7) ? st*12 : 84 + (st-7)*10;
    const int pairs = (st < 7) ? 6 : 5;

    // ---- phase 1 (independent of MLP outputs): stage input rows ----
    const float* xn = x + (size_t)n * CIN * HW * HW;
    stage_row(xn, xs32, row0 - 1, x0, tid);
    stage_row(xn, xs32, row0,     x0, tid);
    stage_row(xn, xs32, row0 + 1, x0, tid);
    stage_row(xn, xs32, row0 + 2, x0, tid);

    // ---- wait for mlp_out grid completion (PDL), then touch g_w/g_bias ----
    asm volatile("griddepcontrol.wait;" ::: "memory");

    {
        const uint32_t* gw = reinterpret_cast<const uint32_t*>(g_w + (size_t)n*MODOUT);
        uint32_t* ws = reinterpret_cast<uint32_t*>(smem + OFF_W);
        for (int i = tid; i < COUT*(KDIM/2); i += 256) {
            const int co = i / 144, k2 = i - co*144;
            ws[co*(WST/2) + k2] = gw[i];
        }
    }
    const int lanehi = lane >> 2;
    const int laneq2 = (lane & 3) * 2;
    const float bias0 = g_bias[n*COUT + lanehi];
    const float bias1 = g_bias[n*COUT + lanehi + 8];
    const float bias2 = g_bias[n*COUT + lanehi + 16];
    const float bias3 = g_bias[n*COUT + lanehi + 24];
    __syncthreads();

    const uint32_t sb   = smem_u32(smem);
    const uint32_t aoff = (uint32_t)(((lane & 15)*WST + (lane >> 4)*8) * 2);
    const uint32_t wbase = sb + OFF_W + aoff;
    const uint32_t xlane = sb + OFF_X +
        (uint32_t)(((w*16 + (lane & 7) + ((lane & 16) ? 8 : 0)) * CIP
                    + ((lane & 8) ? 8 : 0)) * 2);

    uint32_t aA[2][2][4];       // [buf][m-tile][regs]
    uint32_t bB[2][4];          // [buf][regs]: j0 = +0, j1 = +2

#define ALOADX(b, kh, kw, hf) do { \
    const uint32_t c32_ = (uint32_t)(((((kh)*3+(kw))*2+(hf))) * 32u); \
    ldm4(aA[b][0], wbase + c32_); \
    ldm4(aA[b][1], wbase + c32_ + 16*WST*2); \
} while (0)

#define BLOADX(b, slot, kw, hf) do { \
    const uint32_t addr_ = xlane + \
        (uint32_t)(((((slot)*RC + (kw))*CIP) + (hf)*16) * 2); \
    ldm4(bB[b], addr_); \
} while (0)

#define MMA4(r, ab, bb) do { \
    mma_f16(acc[r][0][0], aA[ab][0], bB[bb]); \
    mma_f16(acc[r][1][0], aA[ab][1], bB[bb]); \
    mma_f16(acc[r][0][1], aA[ab][0], bB[bb]+2); \
    mma_f16(acc[r][1][1], aA[ab][1], bB[bb]+2); \
} while (0)

// Pipelined kwh body. Entry: aA[ain]=kh0@(kw,hf), bB[0]=d0@(kw,hf).
// Exit: aA[aot]=kh0@(nkw,nhf), bB[0]=d0-next (@nslot).
#define KWH_BODY(ain, aot, kw, hf, nkw, nhf, nslot) do { \
    BLOADX(1, s_[1], kw, hf);        /* d1 */ \
    ALOADX(aot, 1, kw, hf);          /* kh1 */ \
    MMA4(0, ain, 0);                 /* row0/kh0 @ d0 */ \
    BLOADX(0, s_[2], kw, hf);        /* d2 */ \
    MMA4(1, ain, 1);                 /* row1/kh0 @ d1 */ \
    ALOADX(ain, 2, kw, hf);          /* kh2 */ \
    MMA4(0, aot, 1);                 /* row0/kh1 @ d1 */ \
    BLOADX(1, s_[3], kw, hf);        /* d3 */ \
    MMA4(1, aot, 0);                 /* row1/kh1 @ d2 */ \
    ALOADX(aot, 0, nkw, nhf);        /* next kh0 */ \
    MMA4(0, ain, 0);                 /* row0/kh2 @ d2 */ \
    BLOADX(0, nslot, nkw, nhf);      /* next d0 */ \
    MMA4(1, ain, 1);                 /* row1/kh2 @ d3 */ \
} while (0)

    // strip prologue: first pair's kwh0 entry fragments
    ALOADX(0, 0, 0, 0);
    BLOADX(0, (row0 - 1) & (NSLOT - 1), 0, 0);

    #pragma unroll 1
    for (int t = 0; t < pairs; t++) {
        const int y = row0 + 2*t;
        int s_[4];
        #pragma unroll
        for (int dd = 0; dd < 4; dd++) s_[dd] = (y - 1 + dd) & (NSLOT - 1);

        float acc[2][2][2][4];
        #pragma unroll
        for (int r = 0; r < 2; r++)
            #pragma unroll
            for (int mi = 0; mi < 2; mi++)
                #pragma unroll
                for (int j = 0; j < 2; j++)
                    #pragma unroll
                    for (int q = 0; q < 4; q++) acc[r][mi][j][q] = 0.f;

        // 6 kwh bodies, A-buffer parity alternating; kwh5 tail preloads
        // next pair's kwh0 fragments (next d0 slot = s_[2] = (y+1)&3).
        KWH_BODY(0, 1, 0, 0, 0, 1, s_[0]);
        KWH_BODY(1, 0, 0, 1, 1, 0, s_[0]);
        KWH_BODY(0, 1, 1, 0, 1, 1, s_[0]);
        KWH_BODY(1, 0, 1, 1, 2, 0, s_[0]);
        KWH_BODY(0, 1, 2, 0, 2, 1, s_[0]);
        KWH_BODY(1, 0, 2, 1, 0, 0, s_[2]);

        // ---- epilogue: 2 rows, bias + coalesced float2 stores ----
        #pragma unroll
        for (int r = 0; r < 2; r++) {
            const int yy = y + r;
            const int pxb = x0 + w*16 + laneq2;
            #pragma unroll
            for (int mi = 0; mi < 2; mi++) {
                const float bA = mi ? bias2 : bias0;
                const float bB2 = mi ? bias3 : bias1;
                const int coA = mi*16 + lanehi;
                float* o0 = out + (((size_t)n*COUT + coA)*HW + yy)*HW + pxb;
                #pragma unroll
                for (int j = 0; j < 2; j++) {
                    *reinterpret_cast<float2*>(o0 + 8*j) =
                        make_float2(acc[r][mi][j][0] + bA, acc[r][mi][j][1] + bA);
                    *reinterpret_cast<float2*>(o0 + 8*j + (size_t)8*HW*HW) =
                        make_float2(acc[r][mi][j][2] + bB2, acc[r][mi][j][3] + bB2);
                }
            }
        }

        if (t + 1 < pairs) {
            __syncthreads();
            stage_row(xn, xs32, y + 3, x0, tid);
            stage_row(xn, xs32, y + 4, x0, tid);
            __syncthreads();
        }
    }
#undef ALOADX
#undef BLOADX
#undef MMA4
#undef KWH_BODY
}

// ---------------------------------------------------------------------------
extern "C" void kernel_launch(void* const* d_in, const int* in_sizes, int n_in,
                              void* d_out, int out_size)
{
    const float* x      = (const float*)d_in[0];
    const float* y      = (const float*)d_in[1];
    const float* weight = (const float*)d_in[2];
    const float* fc_w1  = (const float*)d_in[3];
    const float* fc_b1  = (const float*)d_in[4];
    const float* fc_a   = (const float*)d_in[5];
    const float* fc_w2  = (const float*)d_in[6];
    const float* fc_b2  = (const float*)d_in[7];
    const float* b_w1   = (const float*)d_in[8];
    const float* b_b1   = (const float*)d_in[9];
    const float* b_a    = (const float*)d_in[10];
    const float* b_w2   = (const float*)d_in[11];
    const float* b_b2   = (const float*)d_in[12];
    float* out = (float*)d_out;

    cudaFuncSetAttribute(conv_mma,
                         cudaFuncAttributeMaxDynamicSharedMemorySize,
                         CONV_SMEM);

    mlp_hidden<<<dim3(BN, 2), 512>>>(y, fc_w1, fc_b1, fc_a, b_w1, b_b1, b_a);
    mlp_out<<<577, 512>>>(weight, fc_w2, fc_b2, b_w2, b_b2);

    // conv launched with Programmatic Stream Serialization: it may begin
    // before mlp_out completes; conv stages input, then griddepcontrol.wait
    // gates its reads of g_w / g_bias on mlp_out grid completion.
    {
        cudaLaunchConfig_t cfg = {};
        cfg.gridDim  = dim3(111, BN);
        cfg.blockDim = dim3(256);
        cfg.dynamicSmemBytes = CONV_SMEM;
        cfg.stream = 0;
        cudaLaunchAttribute attr[1];
        attr[0].id = cudaLaunchAttributeProgrammaticStreamSerialization;
        attr[0].val.programmaticStreamSerializationAllowed = 1;
        cfg.attrs = attr;
        cfg.numAttrs = 1;
        cudaLaunchKernelEx(&cfg, conv_mma, x, out);
    }
}

// round 17
// speedup vs baseline: 1.3340x; 1.1477x over previous
#include <cuda_runtime.h>
#include <cuda_fp16.h>
#include <math.h>
#include <stdint.h>

#define BN   8
#define CIN  32
#define COUT 32
#define HW   384
#define AUX  128
#define HID  256
#define MODOUT (COUT*CIN*9)   // 9216
#define KDIM 288              // k = tap*32 + ci
#define WST  296              // padded W row stride (conflict-free ldmatrix)

// Scratch (allocation-free rule: __device__ globals)
__device__ float g_bias[BN * COUT];
__device__ float g_h[BN * 2 * HID];        // [n][branch][HID]
__device__ __half g_w[BN * COUT * KDIM];   // [n][co][tap*32+ci] fp16

// ---------------------------------------------------------------------------
// warp-MMA helpers (sm_80-class, valid on compute_103 without 'a')
// ---------------------------------------------------------------------------
__device__ __forceinline__ uint32_t smem_u32(const void* p) {
    uint32_t a;
    asm("{ .reg .u64 t; cvta.to.shared.u64 t, %1; cvt.u32.u64 %0, t; }"
        : "=r"(a) : "l"(p));
    return a;
}
__device__ __forceinline__ void ldm4(uint32_t r[4], uint32_t addr) {
    asm volatile("ldmatrix.sync.aligned.m8n8.x4.shared.b16 {%0,%1,%2,%3}, [%4];"
        : "=r"(r[0]), "=r"(r[1]), "=r"(r[2]), "=r"(r[3]) : "r"(addr));
}
__device__ __forceinline__ void mma_f16(float d[4], const uint32_t a[4],
                                        const uint32_t b[2]) {
    asm volatile("mma.sync.aligned.m16n8k16.row.col.f32.f16.f16.f32 "
        "{%0,%1,%2,%3}, {%4,%5,%6,%7}, {%8,%9}, {%0,%1,%2,%3};"
        : "+f"(d[0]), "+f"(d[1]), "+f"(d[2]), "+f"(d[3])
        : "r"(a[0]), "r"(a[1]), "r"(a[2]), "r"(a[3]), "r"(b[0]), "r"(b[1]));
}

// ---------------------------------------------------------------------------
// MLP kernel 1: hidden layers. grid (8,2), block 512.
// Signals dependents (mlp_out) to launch immediately at entry.
// ---------------------------------------------------------------------------
__global__ void mlp_hidden(const float* __restrict__ y,
                           const float* __restrict__ fc_w1, const float* __restrict__ fc_b1,
                           const float* __restrict__ fc_a_p,
                           const float* __restrict__ b_w1,  const float* __restrict__ b_b1,
                           const float* __restrict__ b_a_p)
{
    asm volatile("griddepcontrol.launch_dependents;");

    __shared__ float y_s[AUX];
    __shared__ float part[512];
    const int n  = blockIdx.x;
    const int br = blockIdx.y;
    const int t  = threadIdx.x;
    const int col = t & 255;
    const int hf  = t >> 8;

    if (t < AUX) y_s[t] = y[n*AUX + t];
    __syncthreads();

    const float* w1 = br ? b_w1 : fc_w1;
    const float* b1 = br ? b_b1 : fc_b1;
    const float  a  = br ? *b_a_p : *fc_a_p;
    const int i0 = hf * 64;

    float acc[8] = {0,0,0,0,0,0,0,0};
    #pragma unroll
    for (int i = 0; i < 64; i += 8) {
        #pragma unroll
        for (int q = 0; q < 8; q++)
            acc[q] = fmaf(y_s[i0+i+q], w1[(i0+i+q)*HID + col], acc[q]);
    }
    part[t] = ((acc[0]+acc[1])+(acc[2]+acc[3]))
            + ((acc[4]+acc[5])+(acc[6]+acc[7]));
    __syncthreads();

    if (t < 256) {
        const float h = part[t] + part[t+256] + b1[t];
        g_h[(n*2 + br)*HID + t] = (h >= 0.f) ? h : a*h;
    }
}

// ---------------------------------------------------------------------------
// MLP kernel 2: output layers. grid 577, block 512.
// PDL-launched early: stages its fc_w2 / b_w2 chunk into smem (independent
// of g_h) BEFORE griddepcontrol.wait, hiding mlp_hidden behind DRAM reads.
// Mod blocks 0..575: 16 j x 8 samples x 4 HID-quarters. Block 576: biases.
// ---------------------------------------------------------------------------
__global__ void mlp_out(const float* __restrict__ weight,
                        const float* __restrict__ fc_w2, const float* __restrict__ fc_b2,
                        const float* __restrict__ b_w2,  const float* __restrict__ b_b2)
{
    // release conv (next PDL dependent) immediately
    asm volatile("griddepcontrol.launch_dependents;");

    __shared__ float h_s[BN * HID];
    __shared__ float part[512];
    __shared__ float w_s[8192];          // mod: 256x16; bias: 256x32
    const int t = threadIdx.x;

    if (blockIdx.x < 576) {
        const int jb = blockIdx.x * 16;
        // ---- phase 1 (independent of g_h): fc_w2 chunk -> smem ----
        #pragma unroll
        for (int i = t; i < 256*16; i += 512) {
            const int hh = i >> 4;
            const int jj = i & 15;
            w_s[i] = fc_w2[(size_t)hh*MODOUT + jb + jj];
        }
        // ---- wait for mlp_hidden grid, then read g_h ----
        asm volatile("griddepcontrol.wait;" ::: "memory");
        #pragma unroll
        for (int i = t; i < BN*HID; i += 512)
            h_s[i] = g_h[((i >> 8)*2)*HID + (i & 255)];
        __syncthreads();

        const int qt = t >> 7;              // HID quarter 0..3
        const int tt = t & 127;
        const int n  = tt >> 4;
        const int jj = tt & 15;
        const float* hp = h_s + n*HID + qt*64;
        const float* wp = w_s + (qt*64)*16 + jj;

        float m[16];
        #pragma unroll
        for (int q = 0; q < 16; q++) m[q] = 0.f;
        #pragma unroll
        for (int hh = 0; hh < 64; hh += 16) {
            #pragma unroll
            for (int q = 0; q < 16; q++)
                m[q] = fmaf(hp[hh+q], wp[(hh+q)*16], m[q]);
        }
        float s = 0.f;
        #pragma unroll
        for (int q = 0; q < 16; q++) s += m[q];
        part[t] = s;
        __syncthreads();

        if (t < 128) {
            const int n2 = t >> 4;
            const int j2 = jb + (t & 15);
            const float mm = part[t] + part[t+128] + part[t+256] + part[t+384]
                           + fc_b2[j2];
            const float sg = 1.f / (1.f + expf(-mm));
            const float wm = sg * weight[j2];
            const int co  = j2 / 288;
            const int r   = j2 - co*288;
            const int ci  = r / 9;
            const int tap = r - ci*9;
            g_w[(n2*COUT + co)*KDIM + tap*32 + ci] = __float2half_rn(wm);
        }
    } else {
        // ---- bias block: preload b_w2 (8192 floats), then wait ----
        #pragma unroll
        for (int i = t; i < HID*COUT; i += 512)
            w_s[i] = b_w2[i];
        asm volatile("griddepcontrol.wait;" ::: "memory");
        #pragma unroll
        for (int i = t; i < BN*HID; i += 512)
            h_s[i] = g_h[((i >> 8)*2 + 1)*HID + (i & 255)];
        __syncthreads();

        if (t < 256) {
            const int n  = t >> 5;
            const int co = t & 31;
            const float* hb = h_s + n*HID;
            float m[8];
            #pragma unroll
            for (int q = 0; q < 8; q++) m[q] = 0.f;
            #pragma unroll
            for (int hh = 0; hh < HID; hh += 8) {
                #pragma unroll
                for (int q = 0; q < 8; q++)
                    m[q] = fmaf(hb[hh+q], w_s[(hh+q)*COUT + co], m[q]);
            }
            float s = 0.f;
            #pragma unroll
            for (int q = 0; q < 8; q++) s += m[q];
            g_bias[n*COUT + co] = s + b_b2[co];
        }
    }
}

// ---------------------------------------------------------------------------
// Conv: mma.sync fp16 single-pass, 2-row blocking, 3 CTAs/SM,
// cross-kwh software pipeline + PDL (input staging before wait).
// ---------------------------------------------------------------------------
#define RC       130
#define CIP      40
#define NSLOT    4
#define SLAB_B   (NSLOT*RC*CIP*2)          // 41600
#define W_BYTES  (COUT*WST*2)              // 18944
#define OFF_W    0
#define OFF_X    (W_BYTES)                 // 18944
#define CONV_SMEM (OFF_X + SLAB_B)         // 60544 -> 3 CTAs/SM
#define NSTG     9                         // ceil(16*RC/256)

__device__ __forceinline__ void stage_row(const float* __restrict__ xn,
                                          uint32_t* __restrict__ xs32,
                                          int gy, int x0, int tid)
{
    const int slot = (gy + NSLOT) & (NSLOT - 1);
    const bool yok = (unsigned)gy < (unsigned)HW;
    float v0[NSTG], v1[NSTG];
    #pragma unroll
    for (int it = 0; it < NSTG; it++) {
        const int i = tid + it*256;
        const int cp  = i / RC;
        const int col = i - cp*RC;
        const int gx  = x0 - 1 + col;
        float f0 = 0.f, f1 = 0.f;
        if (i < 16*RC && yok && (unsigned)gx < (unsigned)HW) {
            const float* p = xn + ((2*cp)*HW + gy)*HW + gx;
            f0 = p[0];
            f1 = p[HW*HW];
        }
        v0[it] = f0; v1[it] = f1;
    }
    #pragma unroll
    for (int it = 0; it < NSTG; it++) {
        const int i = tid + it*256;
        if (i < 16*RC) {
            const int cp  = i / RC;
            const int col = i - cp*RC;
            const __half2 h2 = __floats2half2_rn(v0[it], v1[it]);
            xs32[(slot*RC + col)*(CIP/2) + cp] = *reinterpret_cast<const uint32_t*>(&h2);
        }
    }
}

__global__ void __launch_bounds__(256, 3)
conv_mma(const float* __restrict__ x, float* __restrict__ out)
{
    extern __shared__ char smem[];
    uint32_t* xs32 = reinterpret_cast<uint32_t*>(smem + OFF_X);

    const int tid  = threadIdx.x;
    const int lane = tid & 31;
    const int w    = tid >> 5;
    const int n    = blockIdx.y;
    const int xt   = blockIdx.x % 3;
    const int st   = blockIdx.x / 3;            // 0..36
    const int x0   = xt * 128;
    const int row0  = (st < 7) ? st*12 : 84 + (st-7)*10;
    const int pairs = (st < 7) ? 6 : 5;

    // ---- phase 1 (independent of MLP outputs): stage input rows ----
    const float* xn = x + (size_t)n * CIN * HW * HW;
    stage_row(xn, xs32, row0 - 1, x0, tid);
    stage_row(xn, xs32, row0,     x0, tid);
    stage_row(xn, xs32, row0 + 1, x0, tid);
    stage_row(xn, xs32, row0 + 2, x0, tid);

    // ---- wait for mlp_out grid completion (PDL), then touch g_w/g_bias ----
    asm volatile("griddepcontrol.wait;" ::: "memory");

    {
        const uint32_t* gw = reinterpret_cast<const uint32_t*>(g_w + (size_t)n*MODOUT);
        uint32_t* ws = reinterpret_cast<uint32_t*>(smem + OFF_W);
        for (int i = tid; i < COUT*(KDIM/2); i += 256) {
            const int co = i / 144, k2 = i - co*144;
            ws[co*(WST/2) + k2] = gw[i];
        }
    }
    const int lanehi = lane >> 2;
    const int laneq2 = (lane & 3) * 2;
    const float bias0 = g_bias[n*COUT + lanehi];
    const float bias1 = g_bias[n*COUT + lanehi + 8];
    const float bias2 = g_bias[n*COUT + lanehi + 16];
    const float bias3 = g_bias[n*COUT + lanehi + 24];
    __syncthreads();

    const uint32_t sb   = smem_u32(smem);
    const uint32_t aoff = (uint32_t)(((lane & 15)*WST + (lane >> 4)*8) * 2);
    const uint32_t wbase = sb + OFF_W + aoff;
    const uint32_t xlane = sb + OFF_X +
        (uint32_t)(((w*16 + (lane & 7) + ((lane & 16) ? 8 : 0)) * CIP
                    + ((lane & 8) ? 8 : 0)) * 2);

    uint32_t aA[2][2][4];       // [buf][m-tile][regs]
    uint32_t bB[2][4];          // [buf][regs]: j0 = +0, j1 = +2

#define ALOADX(b, kh, kw, hf) do { \
    const uint32_t c32_ = (uint32_t)(((((kh)*3+(kw))*2+(hf))) * 32u); \
    ldm4(aA[b][0], wbase + c32_); \
    ldm4(aA[b][1], wbase + c32_ + 16*WST*2); \
} while (0)

#define BLOADX(b, slot, kw, hf) do { \
    const uint32_t addr_ = xlane + \
        (uint32_t)(((((slot)*RC + (kw))*CIP) + (hf)*16) * 2); \
    ldm4(bB[b], addr_); \
} while (0)

#define MMA4(r, ab, bb) do { \
    mma_f16(acc[r][0][0], aA[ab][0], bB[bb]); \
    mma_f16(acc[r][1][0], aA[ab][1], bB[bb]); \
    mma_f16(acc[r][0][1], aA[ab][0], bB[bb]+2); \
    mma_f16(acc[r][1][1], aA[ab][1], bB[bb]+2); \
} while (0)

// Pipelined kwh body. Entry: aA[ain]=kh0@(kw,hf), bB[0]=d0@(kw,hf).
// Exit: aA[aot]=kh0@(nkw,nhf), bB[0]=d0-next (@nslot).
#define KWH_BODY(ain, aot, kw, hf, nkw, nhf, nslot) do { \
    BLOADX(1, s_[1], kw, hf);        /* d1 */ \
    ALOADX(aot, 1, kw, hf);          /* kh1 */ \
    MMA4(0, ain, 0);                 /* row0/kh0 @ d0 */ \
    BLOADX(0, s_[2], kw, hf);        /* d2 */ \
    MMA4(1, ain, 1);                 /* row1/kh0 @ d1 */ \
    ALOADX(ain, 2, kw, hf);          /* kh2 */ \
    MMA4(0, aot, 1);                 /* row0/kh1 @ d1 */ \
    BLOADX(1, s_[3], kw, hf);        /* d3 */ \
    MMA4(1, aot, 0);                 /* row1/kh1 @ d2 */ \
    ALOADX(aot, 0, nkw, nhf);        /* next kh0 */ \
    MMA4(0, ain, 0);                 /* row0/kh2 @ d2 */ \
    BLOADX(0, nslot, nkw, nhf);      /* next d0 */ \
    MMA4(1, ain, 1);                 /* row1/kh2 @ d3 */ \
} while (0)

    // strip prologue: first pair's kwh0 entry fragments
    ALOADX(0, 0, 0, 0);
    BLOADX(0, (row0 - 1) & (NSLOT - 1), 0, 0);

    #pragma unroll 1
    for (int t = 0; t < pairs; t++) {
        const int y = row0 + 2*t;
        int s_[4];
        #pragma unroll
        for (int dd = 0; dd < 4; dd++) s_[dd] = (y - 1 + dd) & (NSLOT - 1);

        float acc[2][2][2][4];
        #pragma unroll
        for (int r = 0; r < 2; r++)
            #pragma unroll
            for (int mi = 0; mi < 2; mi++)
                #pragma unroll
                for (int j = 0; j < 2; j++)
                    #pragma unroll
                    for (int q = 0; q < 4; q++) acc[r][mi][j][q] = 0.f;

        // 6 kwh bodies, A-buffer parity alternating; kwh5 tail preloads
        // next pair's kwh0 fragments (next d0 slot = s_[2] = (y+1)&3).
        KWH_BODY(0, 1, 0, 0, 0, 1, s_[0]);
        KWH_BODY(1, 0, 0, 1, 1, 0, s_[0]);
        KWH_BODY(0, 1, 1, 0, 1, 1, s_[0]);
        KWH_BODY(1, 0, 1, 1, 2, 0, s_[0]);
        KWH_BODY(0, 1, 2, 0, 2, 1, s_[0]);
        KWH_BODY(1, 0, 2, 1, 0, 0, s_[2]);

        // ---- epilogue: 2 rows, bias + coalesced float2 stores ----
        #pragma unroll
        for (int r = 0; r < 2; r++) {
            const int yy = y + r;
            const int pxb = x0 + w*16 + laneq2;
            #pragma unroll
            for (int mi = 0; mi < 2; mi++) {
                const float bA = mi ? bias2 : bias0;
                const float bB2 = mi ? bias3 : bias1;
                const int coA = mi*16 + lanehi;
                float* o0 = out + (((size_t)n*COUT + coA)*HW + yy)*HW + pxb;
                #pragma unroll
                for (int j = 0; j < 2; j++) {
                    *reinterpret_cast<float2*>(o0 + 8*j) =
                        make_float2(acc[r][mi][j][0] + bA, acc[r][mi][j][1] + bA);
                    *reinterpret_cast<float2*>(o0 + 8*j + (size_t)8*HW*HW) =
                        make_float2(acc[r][mi][j][2] + bB2, acc[r][mi][j][3] + bB2);
                }
            }
        }

        if (t + 1 < pairs) {
            __syncthreads();
            stage_row(xn, xs32, y + 3, x0, tid);
            stage_row(xn, xs32, y + 4, x0, tid);
            __syncthreads();
        }
    }
#undef ALOADX
#undef BLOADX
#undef MMA4
#undef KWH_BODY
}

// ---------------------------------------------------------------------------
extern "C" void kernel_launch(void* const* d_in, const int* in_sizes, int n_in,
                              void* d_out, int out_size)
{
    const float* x      = (const float*)d_in[0];
    const float* y      = (const float*)d_in[1];
    const float* weight = (const float*)d_in[2];
    const float* fc_w1  = (const float*)d_in[3];
    const float* fc_b1  = (const float*)d_in[4];
    const float* fc_a   = (const float*)d_in[5];
    const float* fc_w2  = (const float*)d_in[6];
    const float* fc_b2  = (const float*)d_in[7];
    const float* b_w1   = (const float*)d_in[8];
    const float* b_b1   = (const float*)d_in[9];
    const float* b_a    = (const float*)d_in[10];
    const float* b_w2   = (const float*)d_in[11];
    const float* b_b2   = (const float*)d_in[12];
    float* out = (float*)d_out;

    cudaFuncSetAttribute(conv_mma,
                         cudaFuncAttributeMaxDynamicSharedMemorySize,
                         CONV_SMEM);

    mlp_hidden<<<dim3(BN, 2), 512>>>(y, fc_w1, fc_b1, fc_a, b_w1, b_b1, b_a);

    // mlp_out PDL-launched: overlaps its fc_w2/b_w2 smem staging with
    // mlp_hidden; griddepcontrol.wait gates its g_h reads.
    {
        cudaLaunchConfig_t cfg = {};
        cfg.gridDim  = dim3(577);
        cfg.blockDim = dim3(512);
        cfg.stream = 0;
        cudaLaunchAttribute attr[1];
        attr[0].id = cudaLaunchAttributeProgrammaticStreamSerialization;
        attr[0].val.programmaticStreamSerializationAllowed = 1;
        cfg.attrs = attr;
        cfg.numAttrs = 1;
        cudaLaunchKernelEx(&cfg, mlp_out, weight, fc_w2, fc_b2, b_w2, b_b2);
    }

    // conv PDL-launched: stages input before griddepcontrol.wait on mlp_out.
    {
        cudaLaunchConfig_t cfg = {};
        cfg.gridDim  = dim3(111, BN);
        cfg.blockDim = dim3(256);
        cfg.dynamicSmemBytes = CONV_SMEM;
        cfg.stream = 0;
        cudaLaunchAttribute attr[1];
        attr[0].id = cudaLaunchAttributeProgrammaticStreamSerialization;
        attr[0].val.programmaticStreamSerializationAllowed = 1;
        cfg.attrs = attr;
        cfg.numAttrs = 1;
        cudaLaunchKernelEx(&cfg, conv_mma, x, out);
    }
}